// round 13
// baseline (speedup 1.0000x reference)
#include <cuda_runtime.h>
#include <cuda_fp16.h>
#include <cstdint>

// Fixed problem shape: N=50000, IN_CH=256, OUT_CH=128, NNZ=800000 per matrix.
#define NNODES 50000
#define FEAT   128
#define IN_CH  256
#define MAXNNZ 800000
#define TOT    (NNODES * FEAT)
#define SLOTS  64                  // per-row bucket capacity (Poisson(16): P(>64) ~ 1e-22)
#define FULLM  0xFFFFFFFFu

typedef unsigned long long ull;

// ---------------------------------------------------------------------------
// Static device scratch. m=0 features, m=1 phi_inv, m=2 phi.
// Intermediates in fp16 (halves L2 gather traffic vs fp32). Cursors are zero
// on first call (static zero-init) and reset in-kernel for the next replay.
// ---------------------------------------------------------------------------
__device__ __half g_buf0[TOT];                        // filtered  [N,128] fp16
__device__ __half g_buf1[TOT];                        // tmp       [N,128] fp16
__device__ __half g_wh[IN_CH * FEAT];                 // W in fp16 (64 KB, L1-resident)
__device__ int    g_cursor[3 * NNODES];               // per-row fill cursors == counts
__device__ int2   g_slots[3 * NNODES * SLOTS];        // (col, val-bits) buckets

// ---------------------------------------------------------------------------
// Packed f32x2 helpers (sm_103a FFMA2 — halves scalar FMA count; the
// mov.b64 packs fold into register-pair allocation).
// ---------------------------------------------------------------------------
__device__ __forceinline__ ull fma_f32x2(ull a, ull b, ull c) {
    ull d;
    asm("fma.rn.f32x2 %0, %1, %2, %3;" : "=l"(d) : "l"(a), "l"(b), "l"(c));
    return d;
}
// half2 (as u32) -> packed f32x2
__device__ __forceinline__ ull h2_up(unsigned h2) {
    ull r;
    asm("{\n\t"
        ".reg .f16 l, h;\n\t"
        ".reg .f32 fl, fh;\n\t"
        "mov.b32 {l, h}, %1;\n\t"
        "cvt.f32.f16 fl, l;\n\t"
        "cvt.f32.f16 fh, h;\n\t"
        "mov.b64 %0, {fl, fh};\n\t"
        "}" : "=l"(r) : "r"(h2));
    return r;
}
__device__ __forceinline__ ull dupf(float v) {
    ull r; asm("mov.b64 %0, {%1, %1};" : "=l"(r) : "f"(v)); return r;
}
__device__ __forceinline__ float2 unpackf2(ull p) {
    float a, b; asm("mov.b64 {%0, %1}, %2;" : "=f"(a), "=f"(b) : "l"(p));
    return make_float2(a, b);
}

// ---------------------------------------------------------------------------
// Convert W (fp32 [256,128]) to fp16 once per launch. 32768 elements.
// ---------------------------------------------------------------------------
__global__ void convert_w_kernel(const float* __restrict__ W) {
    int i = (blockIdx.x * blockDim.x + threadIdx.x) * 2;
    if (i < IN_CH * FEAT) {
        float2 f = *reinterpret_cast<const float2*>(W + i);
        *reinterpret_cast<__half2*>(g_wh + i) = __floats2half2_rn(f.x, f.y);
    }
}

// ---------------------------------------------------------------------------
// Fused bucket-scatter for all three matrices. blockIdx.y selects the matrix.
// 4 nnz per thread for ILP. theta (matrix 2) folds phi @ diag(theta) in.
// ---------------------------------------------------------------------------
__global__ void scatter_kernel(const int*   __restrict__ rows0, const float* __restrict__ vals0, int nnz0,
                               const int*   __restrict__ rows1, const float* __restrict__ vals1, int nnz1,
                               const int*   __restrict__ rows2, const float* __restrict__ vals2, int nnz2,
                               const float* __restrict__ theta) {
    const int m = blockIdx.y;
    const int* rows; const int* cols; const float* vals; int nnz;
    const float* th = nullptr;
    if (m == 0)      { rows = rows0; cols = rows0 + nnz0; vals = vals0; nnz = nnz0; }
    else if (m == 1) { rows = rows1; cols = rows1 + nnz1; vals = vals1; nnz = nnz1; }
    else             { rows = rows2; cols = rows2 + nnz2; vals = vals2; nnz = nnz2; th = theta; }

    int base = (blockIdx.x * blockDim.x + threadIdx.x) * 4;
    if (base >= nnz) return;

    int*  cur   = g_cursor + m * NNODES;
    int2* slots = g_slots + (unsigned)m * (unsigned)(NNODES * SLOTS);

    if (base + 4 <= nnz) {
        int4   r4 = *reinterpret_cast<const int4*>(rows + base);
        int4   c4 = *reinterpret_cast<const int4*>(cols + base);
        float4 v4 = *reinterpret_cast<const float4*>(vals + base);
        int   r[4] = {r4.x, r4.y, r4.z, r4.w};
        int   c[4] = {c4.x, c4.y, c4.z, c4.w};
        float v[4] = {v4.x, v4.y, v4.z, v4.w};
        #pragma unroll
        for (int k = 0; k < 4; k++) {
            float vv = v[k];
            if (th) vv *= __ldg(th + c[k]);
            int pos = atomicAdd(cur + r[k], 1);
            slots[(unsigned)r[k] * SLOTS + (unsigned)pos] = make_int2(c[k], __float_as_int(vv));
        }
    } else {
        for (int i = base; i < nnz && i < base + 4; i++) {
            int r = __ldg(rows + i);
            int c = __ldg(cols + i);
            float vv = __ldg(vals + i);
            if (th) vv *= __ldg(th + c);
            int pos = atomicAdd(cur + r, 1);
            slots[(unsigned)r * SLOTS + (unsigned)pos] = make_int2(c, __float_as_int(vv));
        }
    }
}

// ---------------------------------------------------------------------------
// Gather SpMM: out[row,:] = sum_j v_j * dense[c_j,:]   (F = 128, fp16 rows)
// One warp per row (proven structure): lane i prefetches entry i with ONE
// coalesced 8B load; cols/vals broadcast via shfl so the 4 dense loads per
// batch are fully independent. Math in packed FFMA2 (fp32 lanes).
// Cursor reset in-kernel (no separate zero pass). ReLU fusable.
// ---------------------------------------------------------------------------
template <bool OUT_HALF, bool RELU>
__global__ void spmm_gather_kernel(int m,
                                   const __half* __restrict__ dense,
                                   void*         __restrict__ out_v) {
    int row  = (blockIdx.x * blockDim.x + threadIdx.x) >> 5;
    int lane = threadIdx.x & 31;
    if (row >= NNODES) return;

    const int cidx = m * NNODES + row;
    int cnt = __ldg(g_cursor + cidx);
    if (lane == 0) g_cursor[cidx] = 0;       // reset for the next execution
    if (cnt > SLOTS) cnt = SLOTS;

    const int2* e = g_slots + (unsigned)m * (unsigned)(NNODES * SLOTS)
                           + (unsigned)row * SLOTS;

    // One coalesced load covers entries 0..31 for the whole warp.
    int2 my_e = make_int2(0, 0);
    if (lane < cnt) my_e = __ldg(e + lane);

    // Packed f32x2 accumulators; two sets break the FFMA2 dependency chain.
    ull a0 = 0ull, b0 = 0ull, a1 = 0ull, b1 = 0ull;

    const int n32 = (cnt < 32) ? cnt : 32;
    int i = 0;
    for (; i + 4 <= n32; i += 4) {
        unsigned c0 = (unsigned)__shfl_sync(FULLM, my_e.x, i);
        unsigned c1 = (unsigned)__shfl_sync(FULLM, my_e.x, i + 1);
        unsigned c2 = (unsigned)__shfl_sync(FULLM, my_e.x, i + 2);
        unsigned c3 = (unsigned)__shfl_sync(FULLM, my_e.x, i + 3);
        ull v0 = dupf(__int_as_float(__shfl_sync(FULLM, my_e.y, i)));
        ull v1 = dupf(__int_as_float(__shfl_sync(FULLM, my_e.y, i + 1)));
        ull v2 = dupf(__int_as_float(__shfl_sync(FULLM, my_e.y, i + 2)));
        ull v3 = dupf(__int_as_float(__shfl_sync(FULLM, my_e.y, i + 3)));
        // 4 independent loads in flight
        uint2 r0 = __ldg(reinterpret_cast<const uint2*>(dense + c0 * FEAT) + lane);
        uint2 r1 = __ldg(reinterpret_cast<const uint2*>(dense + c1 * FEAT) + lane);
        uint2 r2 = __ldg(reinterpret_cast<const uint2*>(dense + c2 * FEAT) + lane);
        uint2 r3 = __ldg(reinterpret_cast<const uint2*>(dense + c3 * FEAT) + lane);
        a0 = fma_f32x2(h2_up(r0.x), v0, a0);  b0 = fma_f32x2(h2_up(r0.y), v0, b0);
        a1 = fma_f32x2(h2_up(r1.x), v1, a1);  b1 = fma_f32x2(h2_up(r1.y), v1, b1);
        a0 = fma_f32x2(h2_up(r2.x), v2, a0);  b0 = fma_f32x2(h2_up(r2.y), v2, b0);
        a1 = fma_f32x2(h2_up(r3.x), v3, a1);  b1 = fma_f32x2(h2_up(r3.y), v3, b1);
    }
    for (; i < n32; i++) {
        unsigned c0 = (unsigned)__shfl_sync(FULLM, my_e.x, i);
        ull      v0 = dupf(__int_as_float(__shfl_sync(FULLM, my_e.y, i)));
        uint2 r0 = __ldg(reinterpret_cast<const uint2*>(dense + c0 * FEAT) + lane);
        a0 = fma_f32x2(h2_up(r0.x), v0, a0);  b0 = fma_f32x2(h2_up(r0.y), v0, b0);
    }
    // Rare tail: rows with more than 32 entries (~1e-4 of rows).
    for (; i < cnt; i++) {
        int2 ee = __ldg(e + i);
        ull  vv = dupf(__int_as_float(ee.y));
        uint2 r0 = __ldg(reinterpret_cast<const uint2*>(dense + (unsigned)ee.x * FEAT) + lane);
        a0 = fma_f32x2(h2_up(r0.x), vv, a0);  b0 = fma_f32x2(h2_up(r0.y), vv, b0);
    }

    float2 fa0 = unpackf2(a0), fa1 = unpackf2(a1);
    float2 fb0 = unpackf2(b0), fb1 = unpackf2(b1);
    float4 r;
    r.x = fa0.x + fa1.x;
    r.y = fa0.y + fa1.y;
    r.z = fb0.x + fb1.x;
    r.w = fb0.y + fb1.y;
    if (RELU) {
        r.x = fmaxf(r.x, 0.f); r.y = fmaxf(r.y, 0.f);
        r.z = fmaxf(r.z, 0.f); r.w = fmaxf(r.w, 0.f);
    }

    if (OUT_HALF) {
        __half2 h0 = __floats2half2_rn(r.x, r.y);
        __half2 h1 = __floats2half2_rn(r.z, r.w);
        uint2 packed;
        packed.x = *reinterpret_cast<unsigned*>(&h0);
        packed.y = *reinterpret_cast<unsigned*>(&h1);
        reinterpret_cast<uint2*>((__half*)out_v + (unsigned)row * FEAT)[lane] = packed;
    } else {
        reinterpret_cast<float4*>((float*)out_v + (unsigned)row * FEAT)[lane] = r;
    }
}

// ---------------------------------------------------------------------------
// Launch sequence (graph-capturable, 5 kernels).
// Inputs:
//   0 phi_indices int32[2,NNZ]  1 phi_values f32[NNZ]
//   2 phi_inv_indices           3 phi_inv_values
//   4 feature_indices           5 feature_values
//   6 weight_matrix f32[256,128] 7 theta f32[N]  8 dropout (ignored)
// ---------------------------------------------------------------------------
extern "C" void kernel_launch(void* const* d_in, const int* in_sizes, int n_in,
                              void* d_out, int out_size) {
    const int*   phi_idx    = (const int*)  d_in[0];
    const float* phi_vals   = (const float*)d_in[1];
    const int*   phinv_idx  = (const int*)  d_in[2];
    const float* phinv_vals = (const float*)d_in[3];
    const int*   feat_idx   = (const int*)  d_in[4];
    const float* feat_vals  = (const float*)d_in[5];
    const float* W          = (const float*)d_in[6];
    const float* theta      = (const float*)d_in[7];
    float*       out        = (float*)d_out;

    const int nnz_phi   = in_sizes[1];
    const int nnz_phinv = in_sizes[3];
    const int nnz_feat  = in_sizes[5];

    __half* buf0 = nullptr; __half* buf1 = nullptr; __half* wh = nullptr;
    cudaGetSymbolAddress((void**)&buf0, g_buf0);
    cudaGetSymbolAddress((void**)&buf1, g_buf1);
    cudaGetSymbolAddress((void**)&wh,   g_wh);

    const int B = 256;

    // 1) W -> fp16 (tiny)
    convert_w_kernel<<<(IN_CH * FEAT / 2 + B - 1) / B, B>>>(W);

    // 2) fused bucket scatter for all three matrices
    //    (cursors zero: static init on first call, reset by SpMMs afterwards)
    int nnz_max = nnz_feat;
    if (nnz_phinv > nnz_max) nnz_max = nnz_phinv;
    if (nnz_phi   > nnz_max) nnz_max = nnz_phi;
    dim3 sgrid((nnz_max + 4 * B - 1) / (4 * B), 3);
    scatter_kernel<<<sgrid, B>>>(feat_idx,  feat_vals,  nnz_feat,
                                 phinv_idx, phinv_vals, nnz_phinv,
                                 phi_idx,   phi_vals,   nnz_phi,
                                 theta);

    // 3) three gather SpMMs: f16 W -> f16 buf0 -> f16 buf1 -> f32 out (+ReLU)
    const int SG = (NNODES * 32 + B - 1) / B;    // warp per row
    spmm_gather_kernel<true,  false><<<SG, B>>>(0, wh,   buf0);
    spmm_gather_kernel<true,  false><<<SG, B>>>(1, buf0, buf1);
    spmm_gather_kernel<false, true ><<<SG, B>>>(2, buf1, out);
}

// round 15
// speedup vs baseline: 1.1125x; 1.1125x over previous
#include <cuda_runtime.h>
#include <cuda_fp16.h>
#include <cstdint>

// Fixed problem shape: N=50000, IN_CH=256, OUT_CH=128, NNZ=800000 per matrix.
#define NNODES 50000
#define FEAT   128
#define IN_CH  256
#define MAXNNZ 800000
#define TOT    (NNODES * FEAT)
#define SLOTS  64                  // per-row bucket capacity (Poisson(16): P(>64) ~ 1e-22)
#define FULLM  0xFFFFFFFFu

// ---------------------------------------------------------------------------
// Static device scratch. m=0 features, m=1 phi_inv, m=2 phi.
// Intermediates in fp16 (halves L2 gather traffic). Entries packed to 4 B:
// (val_fp16 << 16) | col_u16  — one shuffle broadcasts a whole entry.
// Cursors zero on first call (static zero-init), reset in-kernel per replay.
// ---------------------------------------------------------------------------
__device__ __half   g_buf0[TOT];                      // filtered  [N,128] fp16
__device__ __half   g_buf1[TOT];                      // tmp       [N,128] fp16
__device__ __half   g_wh[IN_CH * FEAT];               // W in fp16 (64 KB, L1-resident)
__device__ int      g_cursor[3 * NNODES];             // per-row fill cursors == counts
__device__ unsigned g_slots[3 * NNODES * SLOTS];      // packed (val16|col16) buckets

// ---------------------------------------------------------------------------
// Convert W (fp32 [256,128]) to fp16 once per launch. 32768 elements.
// ---------------------------------------------------------------------------
__global__ void convert_w_kernel(const float* __restrict__ W) {
    int i = (blockIdx.x * blockDim.x + threadIdx.x) * 2;
    if (i < IN_CH * FEAT) {
        float2 f = *reinterpret_cast<const float2*>(W + i);
        *reinterpret_cast<__half2*>(g_wh + i) = __floats2half2_rn(f.x, f.y);
    }
}

// ---------------------------------------------------------------------------
// Pack helper: (fp16(val) << 16) | col.
// ---------------------------------------------------------------------------
__device__ __forceinline__ unsigned pack_entry(int col, float val) {
    __half h = __float2half_rn(val);
    unsigned hv = (unsigned)*reinterpret_cast<unsigned short*>(&h);
    return (hv << 16) | (unsigned)col;
}

// ---------------------------------------------------------------------------
// Fused bucket-scatter for all three matrices. blockIdx.y selects the matrix.
// 4 nnz per thread for ILP. theta (matrix 2) folds phi @ diag(theta) in.
// ---------------------------------------------------------------------------
__global__ void scatter_kernel(const int*   __restrict__ rows0, const float* __restrict__ vals0, int nnz0,
                               const int*   __restrict__ rows1, const float* __restrict__ vals1, int nnz1,
                               const int*   __restrict__ rows2, const float* __restrict__ vals2, int nnz2,
                               const float* __restrict__ theta) {
    const int m = blockIdx.y;
    const int* rows; const int* cols; const float* vals; int nnz;
    const float* th = nullptr;
    if (m == 0)      { rows = rows0; cols = rows0 + nnz0; vals = vals0; nnz = nnz0; }
    else if (m == 1) { rows = rows1; cols = rows1 + nnz1; vals = vals1; nnz = nnz1; }
    else             { rows = rows2; cols = rows2 + nnz2; vals = vals2; nnz = nnz2; th = theta; }

    int base = (blockIdx.x * blockDim.x + threadIdx.x) * 4;
    if (base >= nnz) return;

    int*      cur   = g_cursor + m * NNODES;
    unsigned* slots = g_slots + (unsigned)m * (unsigned)(NNODES * SLOTS);

    if (base + 4 <= nnz) {
        int4   r4 = *reinterpret_cast<const int4*>(rows + base);
        int4   c4 = *reinterpret_cast<const int4*>(cols + base);
        float4 v4 = *reinterpret_cast<const float4*>(vals + base);
        int   r[4] = {r4.x, r4.y, r4.z, r4.w};
        int   c[4] = {c4.x, c4.y, c4.z, c4.w};
        float v[4] = {v4.x, v4.y, v4.z, v4.w};
        #pragma unroll
        for (int k = 0; k < 4; k++) {
            float vv = v[k];
            if (th) vv *= __ldg(th + c[k]);
            int pos = atomicAdd(cur + r[k], 1);
            slots[(unsigned)r[k] * SLOTS + (unsigned)pos] = pack_entry(c[k], vv);
        }
    } else {
        for (int i = base; i < nnz && i < base + 4; i++) {
            int r = __ldg(rows + i);
            int c = __ldg(cols + i);
            float vv = __ldg(vals + i);
            if (th) vv *= __ldg(th + c);
            int pos = atomicAdd(cur + r, 1);
            slots[(unsigned)r * SLOTS + (unsigned)pos] = pack_entry(c, vv);
        }
    }
}

// ---------------------------------------------------------------------------
// fp16 row load: lane loads uint2 (4 halves, 8 B) -> warp covers 256 B.
// ---------------------------------------------------------------------------
__device__ __forceinline__ float4 load_row_f16(const __half* base, unsigned c, int lane) {
    uint2 raw = __ldg(reinterpret_cast<const uint2*>(base + c * FEAT) + lane);
    __half2 h0 = *reinterpret_cast<__half2*>(&raw.x);
    __half2 h1 = *reinterpret_cast<__half2*>(&raw.y);
    float2 f0 = __half22float2(h0);
    float2 f1 = __half22float2(h1);
    return make_float4(f0.x, f0.y, f1.x, f1.y);
}

// Unpack a packed entry broadcast: col + fp32 value.
__device__ __forceinline__ void unpack_entry(unsigned u, unsigned& col, float& val) {
    col = u & 0xFFFFu;
    unsigned short hv = (unsigned short)(u >> 16);
    val = __half2float(*reinterpret_cast<__half*>(&hv));
}

// ---------------------------------------------------------------------------
// Gather SpMM (R12 proven structure): out[row,:] = sum_j v_j * dense[c_j,:]
// One warp per row. Lane i prefetches packed entry i with ONE coalesced 4B
// load; ONE shfl per entry broadcasts col+val together. 4 independent dense
// loads in flight per batch. fp32 accumulation. Cursor reset in-kernel.
// ---------------------------------------------------------------------------
template <bool OUT_HALF, bool RELU>
__global__ void spmm_gather_kernel(int m,
                                   const __half* __restrict__ dense,
                                   void*         __restrict__ out_v) {
    int row  = (blockIdx.x * blockDim.x + threadIdx.x) >> 5;
    int lane = threadIdx.x & 31;
    if (row >= NNODES) return;

    const int cidx = m * NNODES + row;
    int cnt = __ldg(g_cursor + cidx);
    if (lane == 0) g_cursor[cidx] = 0;       // reset for the next execution
    if (cnt > SLOTS) cnt = SLOTS;

    const unsigned* e = g_slots + (unsigned)m * (unsigned)(NNODES * SLOTS)
                               + (unsigned)row * SLOTS;

    // One coalesced 4B load covers entries 0..31 for the whole warp.
    unsigned my_e = 0;
    if (lane < cnt) my_e = __ldg(e + lane);

    float4 acc0 = make_float4(0.f, 0.f, 0.f, 0.f);
    float4 acc1 = make_float4(0.f, 0.f, 0.f, 0.f);

    const int n32 = (cnt < 32) ? cnt : 32;
    int i = 0;
    for (; i + 4 <= n32; i += 4) {
        unsigned u0 = __shfl_sync(FULLM, my_e, i);
        unsigned u1 = __shfl_sync(FULLM, my_e, i + 1);
        unsigned u2 = __shfl_sync(FULLM, my_e, i + 2);
        unsigned u3 = __shfl_sync(FULLM, my_e, i + 3);
        unsigned c0, c1, c2, c3; float v0, v1, v2, v3;
        unpack_entry(u0, c0, v0);
        unpack_entry(u1, c1, v1);
        unpack_entry(u2, c2, v2);
        unpack_entry(u3, c3, v3);
        // 4 independent loads in flight
        float4 x0 = load_row_f16(dense, c0, lane);
        float4 x1 = load_row_f16(dense, c1, lane);
        float4 x2 = load_row_f16(dense, c2, lane);
        float4 x3 = load_row_f16(dense, c3, lane);
        acc0.x += v0 * x0.x; acc0.y += v0 * x0.y; acc0.z += v0 * x0.z; acc0.w += v0 * x0.w;
        acc1.x += v1 * x1.x; acc1.y += v1 * x1.y; acc1.z += v1 * x1.z; acc1.w += v1 * x1.w;
        acc0.x += v2 * x2.x; acc0.y += v2 * x2.y; acc0.z += v2 * x2.z; acc0.w += v2 * x2.w;
        acc1.x += v3 * x3.x; acc1.y += v3 * x3.y; acc1.z += v3 * x3.z; acc1.w += v3 * x3.w;
    }
    for (; i < n32; i++) {
        unsigned u0 = __shfl_sync(FULLM, my_e, i);
        unsigned c0; float v0;
        unpack_entry(u0, c0, v0);
        float4 x0 = load_row_f16(dense, c0, lane);
        acc0.x += v0 * x0.x; acc0.y += v0 * x0.y; acc0.z += v0 * x0.z; acc0.w += v0 * x0.w;
    }
    // Rare tail: rows with more than 32 entries (~1e-4 of rows).
    for (; i < cnt; i++) {
        unsigned u0 = __ldg(e + i);
        unsigned c0; float v0;
        unpack_entry(u0, c0, v0);
        float4 x0 = load_row_f16(dense, c0, lane);
        acc0.x += v0 * x0.x; acc0.y += v0 * x0.y; acc0.z += v0 * x0.z; acc0.w += v0 * x0.w;
    }

    float4 r;
    r.x = acc0.x + acc1.x;
    r.y = acc0.y + acc1.y;
    r.z = acc0.z + acc1.z;
    r.w = acc0.w + acc1.w;
    if (RELU) {
        r.x = fmaxf(r.x, 0.f); r.y = fmaxf(r.y, 0.f);
        r.z = fmaxf(r.z, 0.f); r.w = fmaxf(r.w, 0.f);
    }

    if (OUT_HALF) {
        __half2 h0 = __floats2half2_rn(r.x, r.y);
        __half2 h1 = __floats2half2_rn(r.z, r.w);
        uint2 packed;
        packed.x = *reinterpret_cast<unsigned*>(&h0);
        packed.y = *reinterpret_cast<unsigned*>(&h1);
        reinterpret_cast<uint2*>((__half*)out_v + (unsigned)row * FEAT)[lane] = packed;
    } else {
        reinterpret_cast<float4*>((float*)out_v + (unsigned)row * FEAT)[lane] = r;
    }
}

// ---------------------------------------------------------------------------
// Launch sequence (graph-capturable, 5 kernels).
// Inputs:
//   0 phi_indices int32[2,NNZ]  1 phi_values f32[NNZ]
//   2 phi_inv_indices           3 phi_inv_values
//   4 feature_indices           5 feature_values
//   6 weight_matrix f32[256,128] 7 theta f32[N]  8 dropout (ignored)
// ---------------------------------------------------------------------------
extern "C" void kernel_launch(void* const* d_in, const int* in_sizes, int n_in,
                              void* d_out, int out_size) {
    const int*   phi_idx    = (const int*)  d_in[0];
    const float* phi_vals   = (const float*)d_in[1];
    const int*   phinv_idx  = (const int*)  d_in[2];
    const float* phinv_vals = (const float*)d_in[3];
    const int*   feat_idx   = (const int*)  d_in[4];
    const float* feat_vals  = (const float*)d_in[5];
    const float* W          = (const float*)d_in[6];
    const float* theta      = (const float*)d_in[7];
    float*       out        = (float*)d_out;

    const int nnz_phi   = in_sizes[1];
    const int nnz_phinv = in_sizes[3];
    const int nnz_feat  = in_sizes[5];

    __half* buf0 = nullptr; __half* buf1 = nullptr; __half* wh = nullptr;
    cudaGetSymbolAddress((void**)&buf0, g_buf0);
    cudaGetSymbolAddress((void**)&buf1, g_buf1);
    cudaGetSymbolAddress((void**)&wh,   g_wh);

    const int B = 256;

    // 1) W -> fp16 (tiny)
    convert_w_kernel<<<(IN_CH * FEAT / 2 + B - 1) / B, B>>>(W);

    // 2) fused bucket scatter for all three matrices
    //    (cursors zero: static init on first call, reset by SpMMs afterwards)
    int nnz_max = nnz_feat;
    if (nnz_phinv > nnz_max) nnz_max = nnz_phinv;
    if (nnz_phi   > nnz_max) nnz_max = nnz_phi;
    dim3 sgrid((nnz_max + 4 * B - 1) / (4 * B), 3);
    scatter_kernel<<<sgrid, B>>>(feat_idx,  feat_vals,  nnz_feat,
                                 phinv_idx, phinv_vals, nnz_phinv,
                                 phi_idx,   phi_vals,   nnz_phi,
                                 theta);

    // 3) three gather SpMMs: f16 W -> f16 buf0 -> f16 buf1 -> f32 out (+ReLU)
    const int SG = (NNODES * 32 + B - 1) / B;    // warp per row
    spmm_gather_kernel<true,  false><<<SG, B>>>(0, wh,   buf0);
    spmm_gather_kernel<true,  false><<<SG, B>>>(1, buf0, buf1);
    spmm_gather_kernel<false, true ><<<SG, B>>>(2, buf1, out);
}

// round 16
// speedup vs baseline: 1.1369x; 1.0220x over previous
#include <cuda_runtime.h>
#include <cuda_fp16.h>
#include <cstdint>

// Fixed problem shape: N=50000, IN_CH=256, OUT_CH=128, NNZ=800000 per matrix.
#define NNODES 50000
#define FEAT   128
#define IN_CH  256
#define MAXNNZ 800000
#define TOT    (NNODES * FEAT)
#define SLOTS  64                  // per-row bucket capacity (Poisson(16): P(>64) ~ 1e-22)
#define FULLM  0xFFFFFFFFu

// ---------------------------------------------------------------------------
// Static device scratch. m=0 features, m=1 phi_inv, m=2 phi.
// Intermediates fp16; entries packed to 4 B: (val_fp16 << 16) | col_u16.
// Cursors zero on first call (static zero-init), reset in-kernel per replay.
// ---------------------------------------------------------------------------
__device__ __half   g_buf0[TOT];                      // filtered  [N,128] fp16
__device__ __half   g_buf1[TOT];                      // tmp       [N,128] fp16
__device__ __half   g_wh[IN_CH * FEAT];               // W in fp16 (64 KB, L1-resident)
__device__ int      g_cursor[3 * NNODES];             // per-row fill cursors == counts
__device__ unsigned g_slots[3 * NNODES * SLOTS];      // packed (val16|col16) buckets

// ---------------------------------------------------------------------------
// Pack helper: (fp16(val) << 16) | col.
// ---------------------------------------------------------------------------
__device__ __forceinline__ unsigned pack_entry(int col, float val) {
    __half h = __float2half_rn(val);
    unsigned hv = (unsigned)*reinterpret_cast<unsigned short*>(&h);
    return (hv << 16) | (unsigned)col;
}

// ---------------------------------------------------------------------------
// Scatter work for one matrix: participating block sblk, 4 nnz per thread.
// theta != nullptr folds the phi @ diag(theta) column rescale in.
// ---------------------------------------------------------------------------
__device__ __forceinline__ void scatter_work(int sblk, int tid,
                                             const int*   __restrict__ rows,
                                             const float* __restrict__ vals,
                                             int nnz, int m,
                                             const float* __restrict__ theta) {
    const int* cols = rows + nnz;
    int base = (sblk * 256 + tid) * 4;
    if (base >= nnz) return;

    int*      cur   = g_cursor + m * NNODES;
    unsigned* slots = g_slots + (unsigned)m * (unsigned)(NNODES * SLOTS);

    if (base + 4 <= nnz) {
        int4   r4 = *reinterpret_cast<const int4*>(rows + base);
        int4   c4 = *reinterpret_cast<const int4*>(cols + base);
        float4 v4 = *reinterpret_cast<const float4*>(vals + base);
        int   r[4] = {r4.x, r4.y, r4.z, r4.w};
        int   c[4] = {c4.x, c4.y, c4.z, c4.w};
        float v[4] = {v4.x, v4.y, v4.z, v4.w};
        #pragma unroll
        for (int k = 0; k < 4; k++) {
            float vv = v[k];
            if (theta) vv *= __ldg(theta + c[k]);
            int pos = atomicAdd(cur + r[k], 1);
            slots[(unsigned)r[k] * SLOTS + (unsigned)pos] = pack_entry(c[k], vv);
        }
    } else {
        for (int i = base; i < nnz && i < base + 4; i++) {
            int r = __ldg(rows + i);
            int c = __ldg(cols + i);
            float vv = __ldg(vals + i);
            if (theta) vv *= __ldg(theta + c);
            int pos = atomicAdd(cur + r, 1);
            slots[(unsigned)r * SLOTS + (unsigned)pos] = pack_entry(c, vv);
        }
    }
}

// ---------------------------------------------------------------------------
// Kernel 1: scatter matrix 0 (features) + convert W to fp16.
// Blocks [0, sb) scatter; blocks [sb, sb+CONVB) convert.
// ---------------------------------------------------------------------------
__global__ void pre_kernel(const int*   __restrict__ feat_rows,
                           const float* __restrict__ feat_vals,
                           int nnz, int sb,
                           const float* __restrict__ W) {
    if ((int)blockIdx.x < sb) {
        scatter_work(blockIdx.x, threadIdx.x, feat_rows, feat_vals, nnz, 0, nullptr);
    } else {
        int i = (((int)blockIdx.x - sb) * 256 + threadIdx.x) * 2;
        if (i < IN_CH * FEAT) {
            float2 f = *reinterpret_cast<const float2*>(W + i);
            *reinterpret_cast<__half2*>(g_wh + i) = __floats2half2_rn(f.x, f.y);
        }
    }
}

// ---------------------------------------------------------------------------
// fp16 row load: lane loads uint2 (4 halves, 8 B) -> warp covers 256 B.
// ---------------------------------------------------------------------------
__device__ __forceinline__ float4 load_row_f16(const __half* base, unsigned c, int lane) {
    uint2 raw = __ldg(reinterpret_cast<const uint2*>(base + c * FEAT) + lane);
    __half2 h0 = *reinterpret_cast<__half2*>(&raw.x);
    __half2 h1 = *reinterpret_cast<__half2*>(&raw.y);
    float2 f0 = __half22float2(h0);
    float2 f1 = __half22float2(h1);
    return make_float4(f0.x, f0.y, f1.x, f1.y);
}

__device__ __forceinline__ void unpack_entry(unsigned u, unsigned& col, float& val) {
    col = u & 0xFFFFu;
    unsigned short hv = (unsigned short)(u >> 16);
    val = __half2float(*reinterpret_cast<__half*>(&hv));
}

// ---------------------------------------------------------------------------
// Gather SpMM with optional fused scatter prologue for the NEXT stage's
// matrix: first s_blocks blocks scatter their quota, then all blocks do
// spmm rows. R12/R15 proven inner structure: lane-parallel 4B entry
// prefetch, 1 shfl/entry, 4 independent dense loads per batch, fp32 acc.
// ---------------------------------------------------------------------------
template <bool OUT_HALF, bool RELU, bool SCATTER>
__global__ void spmm_gather_kernel(int m,
                                   const __half* __restrict__ dense,
                                   void*         __restrict__ out_v,
                                   const int*    __restrict__ s_rows,
                                   const float*  __restrict__ s_vals,
                                   int s_nnz, int s_m, int s_blocks,
                                   const float*  __restrict__ s_theta) {
    if (SCATTER && (int)blockIdx.x < s_blocks) {
        scatter_work(blockIdx.x, threadIdx.x, s_rows, s_vals, s_nnz, s_m, s_theta);
    }

    int row  = (blockIdx.x * blockDim.x + threadIdx.x) >> 5;
    int lane = threadIdx.x & 31;
    if (row >= NNODES) return;

    const int cidx = m * NNODES + row;
    int cnt = __ldg(g_cursor + cidx);
    if (lane == 0) g_cursor[cidx] = 0;       // reset for the next execution
    if (cnt > SLOTS) cnt = SLOTS;

    const unsigned* e = g_slots + (unsigned)m * (unsigned)(NNODES * SLOTS)
                               + (unsigned)row * SLOTS;

    // One coalesced 4B load covers entries 0..31 for the whole warp.
    unsigned my_e = 0;
    if (lane < cnt) my_e = __ldg(e + lane);

    float4 acc0 = make_float4(0.f, 0.f, 0.f, 0.f);
    float4 acc1 = make_float4(0.f, 0.f, 0.f, 0.f);

    const int n32 = (cnt < 32) ? cnt : 32;
    int i = 0;
    for (; i + 4 <= n32; i += 4) {
        unsigned u0 = __shfl_sync(FULLM, my_e, i);
        unsigned u1 = __shfl_sync(FULLM, my_e, i + 1);
        unsigned u2 = __shfl_sync(FULLM, my_e, i + 2);
        unsigned u3 = __shfl_sync(FULLM, my_e, i + 3);
        unsigned c0, c1, c2, c3; float v0, v1, v2, v3;
        unpack_entry(u0, c0, v0);
        unpack_entry(u1, c1, v1);
        unpack_entry(u2, c2, v2);
        unpack_entry(u3, c3, v3);
        // 4 independent loads in flight
        float4 x0 = load_row_f16(dense, c0, lane);
        float4 x1 = load_row_f16(dense, c1, lane);
        float4 x2 = load_row_f16(dense, c2, lane);
        float4 x3 = load_row_f16(dense, c3, lane);
        acc0.x += v0 * x0.x; acc0.y += v0 * x0.y; acc0.z += v0 * x0.z; acc0.w += v0 * x0.w;
        acc1.x += v1 * x1.x; acc1.y += v1 * x1.y; acc1.z += v1 * x1.z; acc1.w += v1 * x1.w;
        acc0.x += v2 * x2.x; acc0.y += v2 * x2.y; acc0.z += v2 * x2.z; acc0.w += v2 * x2.w;
        acc1.x += v3 * x3.x; acc1.y += v3 * x3.y; acc1.z += v3 * x3.z; acc1.w += v3 * x3.w;
    }
    for (; i < n32; i++) {
        unsigned u0 = __shfl_sync(FULLM, my_e, i);
        unsigned c0; float v0;
        unpack_entry(u0, c0, v0);
        float4 x0 = load_row_f16(dense, c0, lane);
        acc0.x += v0 * x0.x; acc0.y += v0 * x0.y; acc0.z += v0 * x0.z; acc0.w += v0 * x0.w;
    }
    // Rare tail: rows with more than 32 entries (~1e-4 of rows).
    for (; i < cnt; i++) {
        unsigned u0 = __ldg(e + i);
        unsigned c0; float v0;
        unpack_entry(u0, c0, v0);
        float4 x0 = load_row_f16(dense, c0, lane);
        acc0.x += v0 * x0.x; acc0.y += v0 * x0.y; acc0.z += v0 * x0.z; acc0.w += v0 * x0.w;
    }

    float4 r;
    r.x = acc0.x + acc1.x;
    r.y = acc0.y + acc1.y;
    r.z = acc0.z + acc1.z;
    r.w = acc0.w + acc1.w;
    if (RELU) {
        r.x = fmaxf(r.x, 0.f); r.y = fmaxf(r.y, 0.f);
        r.z = fmaxf(r.z, 0.f); r.w = fmaxf(r.w, 0.f);
    }

    if (OUT_HALF) {
        __half2 h0 = __floats2half2_rn(r.x, r.y);
        __half2 h1 = __floats2half2_rn(r.z, r.w);
        uint2 packed;
        packed.x = *reinterpret_cast<unsigned*>(&h0);
        packed.y = *reinterpret_cast<unsigned*>(&h1);
        reinterpret_cast<uint2*>((__half*)out_v + (unsigned)row * FEAT)[lane] = packed;
    } else {
        reinterpret_cast<float4*>((float*)out_v + (unsigned)row * FEAT)[lane] = r;
    }
}

// ---------------------------------------------------------------------------
// Launch sequence (graph-capturable, 4 kernels):
//   pre:   scatter m0 (features) + convert W
//   spmm0: features @ W          + fused scatter m1 (phi_inv)
//   spmm1: phi_inv @ filtered    + fused scatter m2 (phi, theta folded)
//   spmm2: phiD @ tmp + ReLU
// Inputs:
//   0 phi_indices int32[2,NNZ]  1 phi_values f32[NNZ]
//   2 phi_inv_indices           3 phi_inv_values
//   4 feature_indices           5 feature_values
//   6 weight_matrix f32[256,128] 7 theta f32[N]  8 dropout (ignored)
// ---------------------------------------------------------------------------
extern "C" void kernel_launch(void* const* d_in, const int* in_sizes, int n_in,
                              void* d_out, int out_size) {
    const int*   phi_idx    = (const int*)  d_in[0];
    const float* phi_vals   = (const float*)d_in[1];
    const int*   phinv_idx  = (const int*)  d_in[2];
    const float* phinv_vals = (const float*)d_in[3];
    const int*   feat_idx   = (const int*)  d_in[4];
    const float* feat_vals  = (const float*)d_in[5];
    const float* W          = (const float*)d_in[6];
    const float* theta      = (const float*)d_in[7];
    float*       out        = (float*)d_out;

    const int nnz_phi   = in_sizes[1];
    const int nnz_phinv = in_sizes[3];
    const int nnz_feat  = in_sizes[5];

    __half* buf0 = nullptr; __half* buf1 = nullptr; __half* wh = nullptr;
    cudaGetSymbolAddress((void**)&buf0, g_buf0);
    cudaGetSymbolAddress((void**)&buf1, g_buf1);
    cudaGetSymbolAddress((void**)&wh,   g_wh);

    const int B = 256;
    const int sb_feat  = (nnz_feat  + 4 * B - 1) / (4 * B);
    const int sb_phinv = (nnz_phinv + 4 * B - 1) / (4 * B);
    const int sb_phi   = (nnz_phi   + 4 * B - 1) / (4 * B);
    const int CONVB    = (IN_CH * FEAT / 2 + B - 1) / B;

    // 1) scatter features + convert W
    pre_kernel<<<sb_feat + CONVB, B>>>(feat_idx, feat_vals, nnz_feat, sb_feat, W);

    // 2-4) spmm chain; stages 0/1 carry the next stage's scatter as prologue
    const int SG = (NNODES * 32 + B - 1) / B;    // warp per row
    spmm_gather_kernel<true,  false, true ><<<SG, B>>>(
        0, wh,   buf0, phinv_idx, phinv_vals, nnz_phinv, 1, sb_phinv, nullptr);
    spmm_gather_kernel<true,  false, true ><<<SG, B>>>(
        1, buf0, buf1, phi_idx,   phi_vals,   nnz_phi,   2, sb_phi,   theta);
    spmm_gather_kernel<false, true,  false><<<SG, B>>>(
        2, buf1, out,  nullptr,   nullptr,    0,         0, 0,        nullptr);
}

// round 17
// speedup vs baseline: 1.1801x; 1.0380x over previous
#include <cuda_runtime.h>
#include <cuda_fp16.h>
#include <cstdint>

// Fixed problem shape: N=50000, IN_CH=256, OUT_CH=128, NNZ=800000 per matrix.
#define NNODES 50000
#define FEAT   128
#define IN_CH  256
#define MAXNNZ 800000
#define TOT    (NNODES * FEAT)
#define SLOTS  64                  // per-row bucket capacity (Poisson(16): P(>64) ~ 1e-22)
#define FULLM  0xFFFFFFFFu

// ---------------------------------------------------------------------------
// Static device scratch. m=0 features, m=1 phi_inv, m=2 phi.
// Intermediates fp16; entries packed to 4 B: (val_fp16 << 16) | col_u16.
// Cursors zero on first call (static zero-init), reset in-kernel per replay.
// ---------------------------------------------------------------------------
__device__ __half   g_buf0[TOT];                      // filtered  [N,128] fp16
__device__ __half   g_buf1[TOT];                      // tmp       [N,128] fp16
__device__ __half   g_wh[IN_CH * FEAT];               // W in fp16 (64 KB, L1-resident)
__device__ int      g_cursor[3 * NNODES];             // per-row fill cursors == counts
__device__ unsigned g_slots[3 * NNODES * SLOTS];      // packed (val16|col16) buckets

// ---------------------------------------------------------------------------
// Pack helper: (fp16(val) << 16) | col.
// ---------------------------------------------------------------------------
__device__ __forceinline__ unsigned pack_entry(int col, float val) {
    __half h = __float2half_rn(val);
    unsigned hv = (unsigned)*reinterpret_cast<unsigned short*>(&h);
    return (hv << 16) | (unsigned)col;
}

// ---------------------------------------------------------------------------
// Scatter work for one matrix: participating block sblk, 4 nnz per thread.
// theta != nullptr folds the phi @ diag(theta) column rescale in.
// ---------------------------------------------------------------------------
__device__ __forceinline__ void scatter_work(int sblk, int tid,
                                             const int*   __restrict__ rows,
                                             const float* __restrict__ vals,
                                             int nnz, int m,
                                             const float* __restrict__ theta) {
    const int* cols = rows + nnz;
    int base = (sblk * 256 + tid) * 4;
    if (base >= nnz) return;

    int*      cur   = g_cursor + m * NNODES;
    unsigned* slots = g_slots + (unsigned)m * (unsigned)(NNODES * SLOTS);

    if (base + 4 <= nnz) {
        int4   r4 = *reinterpret_cast<const int4*>(rows + base);
        int4   c4 = *reinterpret_cast<const int4*>(cols + base);
        float4 v4 = *reinterpret_cast<const float4*>(vals + base);
        int   r[4] = {r4.x, r4.y, r4.z, r4.w};
        int   c[4] = {c4.x, c4.y, c4.z, c4.w};
        float v[4] = {v4.x, v4.y, v4.z, v4.w};
        #pragma unroll
        for (int k = 0; k < 4; k++) {
            float vv = v[k];
            if (theta) vv *= __ldg(theta + c[k]);
            int pos = atomicAdd(cur + r[k], 1);
            slots[(unsigned)r[k] * SLOTS + (unsigned)pos] = pack_entry(c[k], vv);
        }
    } else {
        for (int i = base; i < nnz && i < base + 4; i++) {
            int r = __ldg(rows + i);
            int c = __ldg(cols + i);
            float vv = __ldg(vals + i);
            if (theta) vv *= __ldg(theta + c);
            int pos = atomicAdd(cur + r, 1);
            slots[(unsigned)r * SLOTS + (unsigned)pos] = pack_entry(c, vv);
        }
    }
}

// ---------------------------------------------------------------------------
// Kernel 1: scatter matrix 0 (features) + convert W to fp16.
// Blocks [0, sb) scatter; blocks [sb, sb+CONVB) convert.
// ---------------------------------------------------------------------------
__global__ void pre_kernel(const int*   __restrict__ feat_rows,
                           const float* __restrict__ feat_vals,
                           int nnz, int sb,
                           const float* __restrict__ W) {
    if ((int)blockIdx.x < sb) {
        scatter_work(blockIdx.x, threadIdx.x, feat_rows, feat_vals, nnz, 0, nullptr);
    } else {
        int i = (((int)blockIdx.x - sb) * 256 + threadIdx.x) * 2;
        if (i < IN_CH * FEAT) {
            float2 f = *reinterpret_cast<const float2*>(W + i);
            *reinterpret_cast<__half2*>(g_wh + i) = __floats2half2_rn(f.x, f.y);
        }
    }
}

// ---------------------------------------------------------------------------
// fp16 row load: lane loads uint2 (4 halves, 8 B) -> warp covers 256 B.
// ---------------------------------------------------------------------------
__device__ __forceinline__ float4 load_row_f16(const __half* base, unsigned c, int lane) {
    uint2 raw = __ldg(reinterpret_cast<const uint2*>(base + c * FEAT) + lane);
    __half2 h0 = *reinterpret_cast<__half2*>(&raw.x);
    __half2 h1 = *reinterpret_cast<__half2*>(&raw.y);
    float2 f0 = __half22float2(h0);
    float2 f1 = __half22float2(h1);
    return make_float4(f0.x, f0.y, f1.x, f1.y);
}

__device__ __forceinline__ void unpack_entry(unsigned u, unsigned& col, float& val) {
    col = u & 0xFFFFu;
    unsigned short hv = (unsigned short)(u >> 16);
    val = __half2float(*reinterpret_cast<__half*>(&hv));
}

// ---------------------------------------------------------------------------
// Gather SpMM with optional fused DOUBLE scatter prologue (both remaining
// matrices ride in spmm0, which gathers from L1-resident W and has the most
// latency slack). Blocks [0,sA) scatter matrix sA_m; [sA, sA+sB) scatter
// sB_m. R12/R15 proven inner structure: lane-parallel 4B entry prefetch,
// 1 shfl/entry, 4 independent dense loads per batch, fp32 accumulation.
// ---------------------------------------------------------------------------
template <bool OUT_HALF, bool RELU, bool SCATTER>
__global__ void spmm_gather_kernel(int m,
                                   const __half* __restrict__ dense,
                                   void*         __restrict__ out_v,
                                   const int*    __restrict__ sA_rows,
                                   const float*  __restrict__ sA_vals,
                                   int sA_nnz, int sA_m, int sA_blocks,
                                   const int*    __restrict__ sB_rows,
                                   const float*  __restrict__ sB_vals,
                                   int sB_nnz, int sB_m, int sB_blocks,
                                   const float*  __restrict__ sB_theta) {
    if (SCATTER) {
        int b = (int)blockIdx.x;
        if (b < sA_blocks) {
            scatter_work(b, threadIdx.x, sA_rows, sA_vals, sA_nnz, sA_m, nullptr);
        } else if (b < sA_blocks + sB_blocks) {
            scatter_work(b - sA_blocks, threadIdx.x, sB_rows, sB_vals, sB_nnz, sB_m, sB_theta);
        }
    }

    int row  = (blockIdx.x * blockDim.x + threadIdx.x) >> 5;
    int lane = threadIdx.x & 31;
    if (row >= NNODES) return;

    const int cidx = m * NNODES + row;
    int cnt = __ldg(g_cursor + cidx);
    if (lane == 0) g_cursor[cidx] = 0;       // reset for the next execution
    if (cnt > SLOTS) cnt = SLOTS;

    const unsigned* e = g_slots + (unsigned)m * (unsigned)(NNODES * SLOTS)
                               + (unsigned)row * SLOTS;

    // One coalesced 4B load covers entries 0..31 for the whole warp.
    unsigned my_e = 0;
    if (lane < cnt) my_e = __ldg(e + lane);

    float4 acc0 = make_float4(0.f, 0.f, 0.f, 0.f);
    float4 acc1 = make_float4(0.f, 0.f, 0.f, 0.f);

    const int n32 = (cnt < 32) ? cnt : 32;
    int i = 0;
    for (; i + 4 <= n32; i += 4) {
        unsigned u0 = __shfl_sync(FULLM, my_e, i);
        unsigned u1 = __shfl_sync(FULLM, my_e, i + 1);
        unsigned u2 = __shfl_sync(FULLM, my_e, i + 2);
        unsigned u3 = __shfl_sync(FULLM, my_e, i + 3);
        unsigned c0, c1, c2, c3; float v0, v1, v2, v3;
        unpack_entry(u0, c0, v0);
        unpack_entry(u1, c1, v1);
        unpack_entry(u2, c2, v2);
        unpack_entry(u3, c3, v3);
        // 4 independent loads in flight
        float4 x0 = load_row_f16(dense, c0, lane);
        float4 x1 = load_row_f16(dense, c1, lane);
        float4 x2 = load_row_f16(dense, c2, lane);
        float4 x3 = load_row_f16(dense, c3, lane);
        acc0.x += v0 * x0.x; acc0.y += v0 * x0.y; acc0.z += v0 * x0.z; acc0.w += v0 * x0.w;
        acc1.x += v1 * x1.x; acc1.y += v1 * x1.y; acc1.z += v1 * x1.z; acc1.w += v1 * x1.w;
        acc0.x += v2 * x2.x; acc0.y += v2 * x2.y; acc0.z += v2 * x2.z; acc0.w += v2 * x2.w;
        acc1.x += v3 * x3.x; acc1.y += v3 * x3.y; acc1.z += v3 * x3.z; acc1.w += v3 * x3.w;
    }
    for (; i < n32; i++) {
        unsigned u0 = __shfl_sync(FULLM, my_e, i);
        unsigned c0; float v0;
        unpack_entry(u0, c0, v0);
        float4 x0 = load_row_f16(dense, c0, lane);
        acc0.x += v0 * x0.x; acc0.y += v0 * x0.y; acc0.z += v0 * x0.z; acc0.w += v0 * x0.w;
    }
    // Rare tail: rows with more than 32 entries (~1e-4 of rows).
    for (; i < cnt; i++) {
        unsigned u0 = __ldg(e + i);
        unsigned c0; float v0;
        unpack_entry(u0, c0, v0);
        float4 x0 = load_row_f16(dense, c0, lane);
        acc0.x += v0 * x0.x; acc0.y += v0 * x0.y; acc0.z += v0 * x0.z; acc0.w += v0 * x0.w;
    }

    float4 r;
    r.x = acc0.x + acc1.x;
    r.y = acc0.y + acc1.y;
    r.z = acc0.z + acc1.z;
    r.w = acc0.w + acc1.w;
    if (RELU) {
        r.x = fmaxf(r.x, 0.f); r.y = fmaxf(r.y, 0.f);
        r.z = fmaxf(r.z, 0.f); r.w = fmaxf(r.w, 0.f);
    }

    if (OUT_HALF) {
        __half2 h0 = __floats2half2_rn(r.x, r.y);
        __half2 h1 = __floats2half2_rn(r.z, r.w);
        uint2 packed;
        packed.x = *reinterpret_cast<unsigned*>(&h0);
        packed.y = *reinterpret_cast<unsigned*>(&h1);
        reinterpret_cast<uint2*>((__half*)out_v + (unsigned)row * FEAT)[lane] = packed;
    } else {
        reinterpret_cast<float4*>((float*)out_v + (unsigned)row * FEAT)[lane] = r;
    }
}

// ---------------------------------------------------------------------------
// Launch sequence (graph-capturable, 4 kernels):
//   pre:   scatter m0 (features) + convert W
//   spmm0: features @ W          + fused scatters m1 (phi_inv) AND m2 (phiD)
//   spmm1: phi_inv @ filtered    (no prologue)
//   spmm2: phiD @ tmp + ReLU
// Inputs:
//   0 phi_indices int32[2,NNZ]  1 phi_values f32[NNZ]
//   2 phi_inv_indices           3 phi_inv_values
//   4 feature_indices           5 feature_values
//   6 weight_matrix f32[256,128] 7 theta f32[N]  8 dropout (ignored)
// ---------------------------------------------------------------------------
extern "C" void kernel_launch(void* const* d_in, const int* in_sizes, int n_in,
                              void* d_out, int out_size) {
    const int*   phi_idx    = (const int*)  d_in[0];
    const float* phi_vals   = (const float*)d_in[1];
    const int*   phinv_idx  = (const int*)  d_in[2];
    const float* phinv_vals = (const float*)d_in[3];
    const int*   feat_idx   = (const int*)  d_in[4];
    const float* feat_vals  = (const float*)d_in[5];
    const float* W          = (const float*)d_in[6];
    const float* theta      = (const float*)d_in[7];
    float*       out        = (float*)d_out;

    const int nnz_phi   = in_sizes[1];
    const int nnz_phinv = in_sizes[3];
    const int nnz_feat  = in_sizes[5];

    __half* buf0 = nullptr; __half* buf1 = nullptr; __half* wh = nullptr;
    cudaGetSymbolAddress((void**)&buf0, g_buf0);
    cudaGetSymbolAddress((void**)&buf1, g_buf1);
    cudaGetSymbolAddress((void**)&wh,   g_wh);

    const int B = 256;
    const int sb_feat  = (nnz_feat  + 4 * B - 1) / (4 * B);
    const int sb_phinv = (nnz_phinv + 4 * B - 1) / (4 * B);
    const int sb_phi   = (nnz_phi   + 4 * B - 1) / (4 * B);
    const int CONVB    = (IN_CH * FEAT / 2 + B - 1) / B;

    // 1) scatter features + convert W
    pre_kernel<<<sb_feat + CONVB, B>>>(feat_idx, feat_vals, nnz_feat, sb_feat, W);

    // 2) spmm0 carries BOTH remaining scatters as prologue
    const int SG = (NNODES * 32 + B - 1) / B;    // warp per row
    spmm_gather_kernel<true,  false, true ><<<SG, B>>>(
        0, wh,   buf0,
        phinv_idx, phinv_vals, nnz_phinv, 1, sb_phinv,
        phi_idx,   phi_vals,   nnz_phi,   2, sb_phi,   theta);
    // 3) spmm1: no prologue
    spmm_gather_kernel<true,  false, false><<<SG, B>>>(
        1, buf0, buf1,
        nullptr, nullptr, 0, 0, 0,
        nullptr, nullptr, 0, 0, 0, nullptr);
    // 4) spmm2: final stage + ReLU, fp32 out
    spmm_gather_kernel<false, true,  false><<<SG, B>>>(
        2, buf1, out,
        nullptr, nullptr, 0, 0, 0,
        nullptr, nullptr, 0, 0, 0, nullptr);
}